// round 4
// baseline (speedup 1.0000x reference)
#include <cuda_runtime.h>
#include <math.h>

#define HH 1024
#define WW 1024
#define PLANES 24           // 8 batch * 3 channels
#define RAD 25
#define TAPS 51

// 100 MB scratch for the horizontal-pass result (no cudaMalloc allowed)
__device__ float g_tmp[(size_t)PLANES * HH * WW];

// ---------------- compile-time gaussian weights -> FFMA immediates ----------
struct WTab { float w[TAPS]; };

__host__ __device__ constexpr double cexp_series(double x) {
    // exp(x) for x in [-1.4, 0]; 40-term series converges far below fp32 eps
    double term = 1.0, sum = 1.0;
    for (int i = 1; i < 40; ++i) { term *= x / (double)i; sum += term; }
    return sum;
}

__host__ __device__ constexpr WTab make_wtab() {
    WTab t{};
    double g[TAPS] = {};
    double s = 0.0;
    for (int i = 0; i < TAPS; ++i) {
        double d = (double)(i - RAD);
        g[i] = cexp_series(-d * d / (2.0 * 15.0 * 15.0));
        s += g[i];
    }
    for (int i = 0; i < TAPS; ++i) t.w[i] = (float)(g[i] / s);
    return t;
}

// ---------------- pass 1: horizontal 51-tap conv ----------------------------
// One block = one image row. 128 threads, 8 outputs/thread (sliding window).
__global__ void __launch_bounds__(128) hpass(const float* __restrict__ x) {
    const int row = blockIdx.x;                       // 0 .. PLANES*HH-1
    const float* src = x + (size_t)row * WW;
    float* dst = g_tmp + (size_t)row * WW;

    __shared__ __align__(16) float s[WW + 2 * RAD + 6];   // 1080, padded for LDS.128

    const int tid = threadIdx.x;
    for (int i = tid; i < WW + 2 * RAD + 6; i += 128) {
        int j = i - RAD;
        s[i] = (j >= 0 && j < WW) ? src[j] : 0.0f;
    }
    __syncthreads();

    constexpr WTab WT = make_wtab();
    const int base = tid * 8;

    float acc[8] = {0.f, 0.f, 0.f, 0.f, 0.f, 0.f, 0.f, 0.f};
    #pragma unroll
    for (int k4 = 0; k4 < 15; ++k4) {               // window k = 0..59 (58 used)
        float4 v4 = *reinterpret_cast<const float4*>(&s[base + 4 * k4]);
        float vv[4] = {v4.x, v4.y, v4.z, v4.w};
        #pragma unroll
        for (int q = 0; q < 4; ++q) {
            const int k = 4 * k4 + q;
            #pragma unroll
            for (int i = 0; i < 8; ++i) {
                if (k - i >= 0 && k - i <= 2 * RAD)
                    acc[i] += WT.w[k - i] * vv[q];  // compile-time weight -> imm
            }
        }
    }

    float4 o0 = make_float4(acc[0], acc[1], acc[2], acc[3]);
    float4 o1 = make_float4(acc[4], acc[5], acc[6], acc[7]);
    reinterpret_cast<float4*>(dst + base)[0] = o0;
    reinterpret_cast<float4*>(dst + base)[1] = o1;
}

// ---------------- pass 2: vertical 51-tap conv + screen blend ---------------
// Block: 128 cols x 16 output rows. smem tile: 66 rows x 128 cols.
#define TY 16
#define TX 128
#define SROWS (TY + 2 * RAD)    // 66

__global__ void __launch_bounds__(128) vpass(const float* __restrict__ x,
                                             const float* __restrict__ amt_p,
                                             float* __restrict__ out) {
    __shared__ __align__(16) float s[SROWS * TX];

    const int tid = threadIdx.x;
    const int plane = blockIdx.z;
    const int x0 = blockIdx.x * TX;
    const int y0 = blockIdx.y * TY;
    const float* tp = g_tmp + (size_t)plane * HH * WW;

    // Cooperative float4 load of the 66x128 tile (rows 4-at-a-time)
    const int lrow = tid >> 5;           // 0..3
    const int lc4  = (tid & 31) * 4;     // 0..124
    #pragma unroll
    for (int r0 = 0; r0 < SROWS; r0 += 4) {
        int r = r0 + lrow;
        if (r < SROWS) {
            int gy = y0 - RAD + r;
            float4 v = make_float4(0.f, 0.f, 0.f, 0.f);
            if (gy >= 0 && gy < HH)
                v = *reinterpret_cast<const float4*>(tp + (size_t)gy * WW + x0 + lc4);
            *reinterpret_cast<float4*>(&s[r * TX + lc4]) = v;
        }
    }
    __syncthreads();

    constexpr WTab WT = make_wtab();
    float acc[TY] = {0.f, 0.f, 0.f, 0.f, 0.f, 0.f, 0.f, 0.f,
                     0.f, 0.f, 0.f, 0.f, 0.f, 0.f, 0.f, 0.f};
    #pragma unroll
    for (int k = 0; k < SROWS; ++k) {
        float v = s[k * TX + tid];       // conflict-free (stride-1 across lanes)
        #pragma unroll
        for (int i = 0; i < TY; ++i) {
            if (k - i >= 0 && k - i <= 2 * RAD)
                acc[i] += WT.w[k - i] * v;
        }
    }

    // amount = sigmoid(param) * 0.4 ; glow = blur * 1.2
    // result = clip(x + blur * (1.2*amount) * (1 - x), 0, 1)
    const float a = amt_p[0];
    const float amount = 0.4f / (1.0f + expf(-a));
    const float kk = 1.2f * amount;

    const float* xp = x + (size_t)plane * HH * WW;
    float* op = out + (size_t)plane * HH * WW;

    #pragma unroll
    for (int i = 0; i < TY; ++i) {
        const size_t off = (size_t)(y0 + i) * WW + x0 + tid;
        float xv = xp[off];
        float r = xv + acc[i] * kk * (1.0f - xv);
        r = fminf(fmaxf(r, 0.0f), 1.0f);
        op[off] = r;
    }
}

extern "C" void kernel_launch(void* const* d_in, const int* in_sizes, int n_in,
                              void* d_out, int out_size) {
    const float* x   = (const float*)d_in[0];
    const float* amt = (const float*)d_in[1];
    float* out = (float*)d_out;

    hpass<<<PLANES * HH, 128>>>(x);
    dim3 grid(WW / TX, HH / TY, PLANES);
    vpass<<<grid, 128>>>(x, amt, out);
}